// round 14
// baseline (speedup 1.0000x reference)
#include <cuda_runtime.h>
#include <cstdint>

// Problem constants (shapes fixed by the dataset)
#define BATCH    2
#define Hh       64
#define Ww       64
#define Cc       128
#define HO       32
#define WO       32
#define NPOOL    131072           // HO*WO*C per batch
#define NOUT     32
#define NIN      524288           // H*W*C per batch  (64*64*128)
#define WZ       33554432LL       // BATCH*NIN*NOUT (one w_zero tensor)
#define OFF_BU   (WZ)             // 64 floats
#define OFF_BL   (2*WZ + 64)      // 64 floats

#define RBLKS    512              // reduction blocks per batch
#define RB       (BATCH * RBLKS)  // 1024 reduce blocks
#define NTHREADS 256

// Scratch (no device allocs allowed)
__device__ float g_bu[BATCH * NPOOL];   // pooled upper bounds (1 MB)
__device__ float g_bl[BATCH * NPOOL];   // pooled lower bounds (1 MB)
__device__ float g_pu[RB * NOUT];
__device__ float g_pl[RB * NOUT];
__device__ unsigned int g_ctr = 0;

// ---------------------------------------------------------------------------
// 0) Pre-pool kernel: 2x2 maxpool of u_c and l_c into scratch.
//    Fully coalesced (consecutive threads -> consecutive channel c).
// ---------------------------------------------------------------------------
__global__ void __launch_bounds__(256)
pool_kernel(const float* __restrict__ uc, const float* __restrict__ lc) {
    int idx = blockIdx.x * 256 + threadIdx.x;   // 0 .. BATCH*NPOOL-1
    int b = idx >> 17;             // / NPOOL
    int p = idx & (NPOOL - 1);
    int c  = p & (Cc - 1);
    int ow = (p >> 7) & (WO - 1);
    int oh = p >> 12;
    size_t base = (((size_t)b * Hh + oh * 2) * Ww + ow * 2) * Cc + c;
    const size_t rs = (size_t)Ww * Cc;   // 8192

    float u0 = __ldg(&uc[base]);
    float u1 = __ldg(&uc[base + Cc]);
    float u2 = __ldg(&uc[base + rs]);
    float u3 = __ldg(&uc[base + rs + Cc]);
    float l0 = __ldg(&lc[base]);
    float l1 = __ldg(&lc[base + Cc]);
    float l2 = __ldg(&lc[base + rs]);
    float l3 = __ldg(&lc[base + rs + Cc]);
    g_bu[idx] = fmaxf(fmaxf(u0, u1), fmaxf(u2, u3));
    g_bl[idx] = fmaxf(fmaxf(l0, l1), fmaxf(l2, l3));
}

// ---------------------------------------------------------------------------
// 1) Reduction kernel. 1024 blocks x 256 threads; warp handles 32 p
//    (8 iters x 4 p); lane -> (pg = lane>>3, j0 = (lane&7)*4).
//    Bounds for the warp's 32 p are preloaded ONCE (1 scalar load pair per
//    lane) and delivered per-iteration via __shfl_sync -> hot loop issues
//    only the 2 coalesced LDG.128 weight loads (512B/warp each tensor).
//    max(w,0)*bu + min(w,0)*bl == w * (w>=0 ? bu : bl).
//    Last block (atomic counter) does final reduce + bias writes; those land
//    outside the concurrently-memset regions, so no race.
// ---------------------------------------------------------------------------
__global__ void __launch_bounds__(NTHREADS)
reduce_kernel(const float* __restrict__ wu,
              const float* __restrict__ wl,
              const float* __restrict__ bou,
              const float* __restrict__ bol,
              float* __restrict__ out) {
    int blk  = blockIdx.x;
    int b    = blk >> 9;               // / RBLKS
    int cb   = blk & (RBLKS - 1);
    int warp = threadIdx.x >> 5;
    int lane = threadIdx.x & 31;
    int pg   = lane >> 3;              // 0..3: which p in the group of 4
    int j0   = (lane & 7) * 4;         // 4 output columns per lane

    const float* __restrict__ wub = wu + (size_t)b * NPOOL * NOUT;
    const float* __restrict__ wlb = wl + (size_t)b * NPOOL * NOUT;

    const int P_PER_BLK  = NPOOL / RBLKS;    // 256
    const int P_PER_WARP = P_PER_BLK / 8;    // 32
    int p0 = cb * P_PER_BLK + warp * P_PER_WARP;

    // one bound pair per lane covers the warp's entire 32-p slice
    float mybu = __ldg(&g_bu[b * NPOOL + p0 + lane]);
    float mybl = __ldg(&g_bl[b * NPOOL + p0 + lane]);

    float au0 = 0.f, au1 = 0.f, au2 = 0.f, au3 = 0.f;
    float al0 = 0.f, al1 = 0.f, al2 = 0.f, al3 = 0.f;

    #pragma unroll
    for (int it = 0; it < P_PER_WARP / 4; it++) {   // 8 iters, 4 p each
        int pl = it * 4 + pg;                       // 0..31 within warp slice
        float bu = __shfl_sync(0xffffffffu, mybu, pl);
        float bl = __shfl_sync(0xffffffffu, mybl, pl);
        size_t wbase = (size_t)(p0 + pl) * NOUT + j0;
        float4 a  = __ldcs((const float4*)&wub[wbase]);
        float4 c4 = __ldcs((const float4*)&wlb[wbase]);
        au0 += a.x  * (a.x  >= 0.f ? bu : bl);
        au1 += a.y  * (a.y  >= 0.f ? bu : bl);
        au2 += a.z  * (a.z  >= 0.f ? bu : bl);
        au3 += a.w  * (a.w  >= 0.f ? bu : bl);
        al0 += c4.x * (c4.x >= 0.f ? bl : bu);
        al1 += c4.y * (c4.y >= 0.f ? bl : bu);
        al2 += c4.z * (c4.z >= 0.f ? bl : bu);
        al3 += c4.w * (c4.w >= 0.f ? bl : bu);
    }

    // combine the 4 p-groups (lanes l, l+8, l+16, l+24 share the same j's)
    #pragma unroll
    for (int ofs = 8; ofs < 32; ofs <<= 1) {
        au0 += __shfl_xor_sync(0xffffffffu, au0, ofs);
        au1 += __shfl_xor_sync(0xffffffffu, au1, ofs);
        au2 += __shfl_xor_sync(0xffffffffu, au2, ofs);
        au3 += __shfl_xor_sync(0xffffffffu, au3, ofs);
        al0 += __shfl_xor_sync(0xffffffffu, al0, ofs);
        al1 += __shfl_xor_sync(0xffffffffu, al1, ofs);
        al2 += __shfl_xor_sync(0xffffffffu, al2, ofs);
        al3 += __shfl_xor_sync(0xffffffffu, al3, ofs);
    }

    __shared__ float su[8][32];
    __shared__ float sl[8][32];
    if (lane < 8) {
        su[warp][j0 + 0] = au0; su[warp][j0 + 1] = au1;
        su[warp][j0 + 2] = au2; su[warp][j0 + 3] = au3;
        sl[warp][j0 + 0] = al0; sl[warp][j0 + 1] = al1;
        sl[warp][j0 + 2] = al2; sl[warp][j0 + 3] = al3;
    }
    __syncthreads();

    __shared__ bool s_last;
    if (threadIdx.x == 0) s_last = false;
    if (warp == 0) {
        float s1 = 0.f, s2 = 0.f;
        #pragma unroll
        for (int i = 0; i < 8; i++) { s1 += su[i][lane]; s2 += sl[i][lane]; }
        g_pu[blk * NOUT + lane] = s1;
        g_pl[blk * NOUT + lane] = s2;
    }
    __syncthreads();
    if (threadIdx.x == 0) {
        __threadfence();       // release partials
        unsigned int prev = atomicAdd(&g_ctr, 1u);
        if (prev == RB - 1) s_last = true;
    }
    __syncthreads();
    if (!s_last) return;

    // ---------------- last block: final reduce + bias writes ----------------
    __threadfence();           // acquire all partials
    {
        int t  = threadIdx.x;          // 0..255
        int j  = t & 31;
        int bb = (t >> 5) & 1;
        int kg = t >> 6;               // 0..3 -> 128 partials each
        float s1 = 0.f, s2 = 0.f;
        #pragma unroll 8
        for (int k = kg * 128; k < kg * 128 + 128; k++) {
            s1 += g_pu[(bb * RBLKS + k) * NOUT + j];
            s2 += g_pl[(bb * RBLKS + k) * NOUT + j];
        }
        __shared__ float shu[4][64];
        __shared__ float shl[4][64];
        shu[kg][bb * 32 + j] = s1;
        shl[kg][bb * 32 + j] = s2;
        __syncthreads();
        if (kg == 0) {
            float a = 0.f, c = 0.f;
            #pragma unroll
            for (int i = 0; i < 4; i++) { a += shu[i][bb * 32 + j]; c += shl[i][bb * 32 + j]; }
            out[OFF_BU + bb * NOUT + j] = a + __ldg(&bou[bb * NOUT + j]);
            out[OFF_BL + bb * NOUT + j] = c + __ldg(&bol[bb * NOUT + j]);
        }
        if (threadIdx.x == 0) g_ctr = 0;   // reset for next graph replay
    }
}

// ---------------------------------------------------------------------------
// Host-side resources for the capture fork (host objects only; created once
// on the first, non-capturing correctness call).
// ---------------------------------------------------------------------------
static cudaStream_t g_s2;
static cudaEvent_t  g_evFork, g_evJoin;
static bool g_res_ready = false;

// ---------------------------------------------------------------------------
// Inputs (metadata order): y, x_0, u_c, l_c, w_out_u, b_out_u, w_out_l, b_out_l
// Output: concat of [w_zero (WZ), b_out_u_ (64), w_zero (WZ), b_out_l_ (64)]
//
// Structure: fork the zero-fill (two memset nodes skipping the bias windows)
// onto a side stream; main stream runs pool -> reduce concurrently; join.
// Bias writes and memset ranges are disjoint -> race-free.
// ---------------------------------------------------------------------------
extern "C" void kernel_launch(void* const* d_in, const int* in_sizes, int n_in,
                              void* d_out, int out_size) {
    const float* u_c  = (const float*)d_in[2];
    const float* l_c  = (const float*)d_in[3];
    const float* wu   = (const float*)d_in[4];
    const float* bou  = (const float*)d_in[5];
    const float* wl   = (const float*)d_in[6];
    const float* bol  = (const float*)d_in[7];
    float* out = (float*)d_out;

    if (!g_res_ready) {
        cudaStreamCreateWithFlags(&g_s2, cudaStreamNonBlocking);
        cudaEventCreateWithFlags(&g_evFork, cudaEventDisableTiming);
        cudaEventCreateWithFlags(&g_evJoin, cudaEventDisableTiming);
        g_res_ready = true;
    }

    // ---- fork side stream into the (possibly capturing) main stream ----
    cudaEventRecord(g_evFork, 0);
    cudaStreamWaitEvent(g_s2, g_evFork, 0);

    // ---- branch A (side stream): zero-fill, skipping the two bias windows ----
    cudaMemsetAsync(out, 0, (size_t)WZ * sizeof(float), g_s2);                // [0, WZ)
    cudaMemsetAsync(out + WZ + 64, 0, (size_t)WZ * sizeof(float), g_s2);      // [WZ+64, 2WZ+64)

    // ---- branch B (main stream): pool -> interval reduction + bias writes ----
    pool_kernel<<<BATCH * NPOOL / 256, 256, 0, 0>>>(u_c, l_c);
    reduce_kernel<<<RB, NTHREADS, 0, 0>>>(wu, wl, bou, bol, out);

    // ---- join ----
    cudaEventRecord(g_evJoin, g_s2);
    cudaStreamWaitEvent(0, g_evJoin, 0);
}

// round 16
// speedup vs baseline: 1.0194x; 1.0194x over previous
#include <cuda_runtime.h>
#include <cstdint>

// Problem constants (shapes fixed by the dataset)
#define BATCH    2
#define Hh       64
#define Ww       64
#define Cc       128
#define HO       32
#define WO       32
#define NPOOL    131072           // HO*WO*C per batch
#define NOUT     32
#define NIN      524288           // H*W*C per batch  (64*64*128)
#define WZ       33554432LL       // BATCH*NIN*NOUT (one w_zero tensor)
#define OFF_BU   (WZ)             // 64 floats
#define OFF_BL   (2*WZ + 64)      // 64 floats

#define RBLKS    512              // reduction blocks per batch
#define RB       (BATCH * RBLKS)  // 1024 reduce blocks
#define NTHREADS 256

// Scratch (no device allocs allowed)
__device__ float g_bu[BATCH * NPOOL];   // pooled upper bounds (1 MB)
__device__ float g_bl[BATCH * NPOOL];   // pooled lower bounds (1 MB)
__device__ float g_pu[RB * NOUT];
__device__ float g_pl[RB * NOUT];
__device__ unsigned int g_ctr = 0;

// ---------------------------------------------------------------------------
// 0) Pre-pool kernel: 2x2 maxpool of u_c and l_c into scratch.
//    Fully coalesced (consecutive threads -> consecutive channel c).
// ---------------------------------------------------------------------------
__global__ void __launch_bounds__(256)
pool_kernel(const float* __restrict__ uc, const float* __restrict__ lc) {
    int idx = blockIdx.x * 256 + threadIdx.x;   // 0 .. BATCH*NPOOL-1
    int b = idx >> 17;             // / NPOOL
    int p = idx & (NPOOL - 1);
    int c  = p & (Cc - 1);
    int ow = (p >> 7) & (WO - 1);
    int oh = p >> 12;
    size_t base = (((size_t)b * Hh + oh * 2) * Ww + ow * 2) * Cc + c;
    const size_t rs = (size_t)Ww * Cc;   // 8192

    float u0 = __ldg(&uc[base]);
    float u1 = __ldg(&uc[base + Cc]);
    float u2 = __ldg(&uc[base + rs]);
    float u3 = __ldg(&uc[base + rs + Cc]);
    float l0 = __ldg(&lc[base]);
    float l1 = __ldg(&lc[base + Cc]);
    float l2 = __ldg(&lc[base + rs]);
    float l3 = __ldg(&lc[base + rs + Cc]);
    g_bu[idx] = fmaxf(fmaxf(u0, u1), fmaxf(u2, u3));
    g_bl[idx] = fmaxf(fmaxf(l0, l1), fmaxf(l2, l3));
}

// ---------------------------------------------------------------------------
// 1) Reduction kernel (R12 hot loop — best isolated measurement: 22.7us).
//    1024 blocks x 256 threads; warp handles 32 p (8 iters x 4 p); lane ->
//    (pg = lane>>3, j0 = (lane&7)*4). Per iter: 2 scalar L2-resident bound
//    loads + 2 coalesced LDG.128 weight loads.
//    max(w,0)*bu + min(w,0)*bl == w * (w>=0 ? bu : bl).
//    Last block (atomic counter) does final reduce + bias writes; those land
//    outside the concurrently-memset regions, so no race.
// ---------------------------------------------------------------------------
__global__ void __launch_bounds__(NTHREADS)
reduce_kernel(const float* __restrict__ wu,
              const float* __restrict__ wl,
              const float* __restrict__ bou,
              const float* __restrict__ bol,
              float* __restrict__ out) {
    int blk  = blockIdx.x;
    int b    = blk >> 9;               // / RBLKS
    int cb   = blk & (RBLKS - 1);
    int warp = threadIdx.x >> 5;
    int lane = threadIdx.x & 31;
    int pg   = lane >> 3;              // 0..3: which p in the group of 4
    int j0   = (lane & 7) * 4;         // 4 output columns per lane

    const float* __restrict__ wub = wu + (size_t)b * NPOOL * NOUT;
    const float* __restrict__ wlb = wl + (size_t)b * NPOOL * NOUT;
    const float* __restrict__ bub = g_bu + b * NPOOL;
    const float* __restrict__ blb = g_bl + b * NPOOL;

    const int P_PER_BLK  = NPOOL / RBLKS;    // 256
    const int P_PER_WARP = P_PER_BLK / 8;    // 32
    int p0 = cb * P_PER_BLK + warp * P_PER_WARP;

    float au0 = 0.f, au1 = 0.f, au2 = 0.f, au3 = 0.f;
    float al0 = 0.f, al1 = 0.f, al2 = 0.f, al3 = 0.f;

    #pragma unroll 4
    for (int it = 0; it < P_PER_WARP / 4; it++) {   // 8 iters, 4 p each
        int p = p0 + it * 4 + pg;
        float bu = __ldg(&bub[p]);
        float bl = __ldg(&blb[p]);
        size_t wbase = (size_t)p * NOUT + j0;
        float4 a  = __ldcs((const float4*)&wub[wbase]);
        float4 c4 = __ldcs((const float4*)&wlb[wbase]);
        au0 += a.x  * (a.x  >= 0.f ? bu : bl);
        au1 += a.y  * (a.y  >= 0.f ? bu : bl);
        au2 += a.z  * (a.z  >= 0.f ? bu : bl);
        au3 += a.w  * (a.w  >= 0.f ? bu : bl);
        al0 += c4.x * (c4.x >= 0.f ? bl : bu);
        al1 += c4.y * (c4.y >= 0.f ? bl : bu);
        al2 += c4.z * (c4.z >= 0.f ? bl : bu);
        al3 += c4.w * (c4.w >= 0.f ? bl : bu);
    }

    // combine the 4 p-groups (lanes l, l+8, l+16, l+24 share the same j's)
    #pragma unroll
    for (int ofs = 8; ofs < 32; ofs <<= 1) {
        au0 += __shfl_xor_sync(0xffffffffu, au0, ofs);
        au1 += __shfl_xor_sync(0xffffffffu, au1, ofs);
        au2 += __shfl_xor_sync(0xffffffffu, au2, ofs);
        au3 += __shfl_xor_sync(0xffffffffu, au3, ofs);
        al0 += __shfl_xor_sync(0xffffffffu, al0, ofs);
        al1 += __shfl_xor_sync(0xffffffffu, al1, ofs);
        al2 += __shfl_xor_sync(0xffffffffu, al2, ofs);
        al3 += __shfl_xor_sync(0xffffffffu, al3, ofs);
    }

    __shared__ float su[8][32];
    __shared__ float sl[8][32];
    if (lane < 8) {
        su[warp][j0 + 0] = au0; su[warp][j0 + 1] = au1;
        su[warp][j0 + 2] = au2; su[warp][j0 + 3] = au3;
        sl[warp][j0 + 0] = al0; sl[warp][j0 + 1] = al1;
        sl[warp][j0 + 2] = al2; sl[warp][j0 + 3] = al3;
    }
    __syncthreads();

    __shared__ bool s_last;
    if (threadIdx.x == 0) s_last = false;
    if (warp == 0) {
        float s1 = 0.f, s2 = 0.f;
        #pragma unroll
        for (int i = 0; i < 8; i++) { s1 += su[i][lane]; s2 += sl[i][lane]; }
        g_pu[blk * NOUT + lane] = s1;
        g_pl[blk * NOUT + lane] = s2;
    }
    __syncthreads();
    if (threadIdx.x == 0) {
        __threadfence();       // release partials
        unsigned int prev = atomicAdd(&g_ctr, 1u);
        if (prev == RB - 1) s_last = true;
    }
    __syncthreads();
    if (!s_last) return;

    // ---------------- last block: final reduce + bias writes ----------------
    __threadfence();           // acquire all partials
    {
        int t  = threadIdx.x;          // 0..255
        int j  = t & 31;
        int bb = (t >> 5) & 1;
        int kg = t >> 6;               // 0..3 -> 128 partials each
        float s1 = 0.f, s2 = 0.f;
        #pragma unroll 8
        for (int k = kg * 128; k < kg * 128 + 128; k++) {
            s1 += g_pu[(bb * RBLKS + k) * NOUT + j];
            s2 += g_pl[(bb * RBLKS + k) * NOUT + j];
        }
        __shared__ float shu[4][64];
        __shared__ float shl[4][64];
        shu[kg][bb * 32 + j] = s1;
        shl[kg][bb * 32 + j] = s2;
        __syncthreads();
        if (kg == 0) {
            float a = 0.f, c = 0.f;
            #pragma unroll
            for (int i = 0; i < 4; i++) { a += shu[i][bb * 32 + j]; c += shl[i][bb * 32 + j]; }
            out[OFF_BU + bb * NOUT + j] = a + __ldg(&bou[bb * NOUT + j]);
            out[OFF_BL + bb * NOUT + j] = c + __ldg(&bol[bb * NOUT + j]);
        }
        if (threadIdx.x == 0) g_ctr = 0;   // reset for next graph replay
    }
}

// ---------------------------------------------------------------------------
// Host-side resources for the capture fork (host objects only; created once
// on the first, non-capturing correctness call).
// ---------------------------------------------------------------------------
static cudaStream_t g_s2, g_s3;
static cudaEvent_t  g_evFork, g_evJoin2, g_evJoin3;
static bool g_res_ready = false;

// ---------------------------------------------------------------------------
// Inputs (metadata order): y, x_0, u_c, l_c, w_out_u, b_out_u, w_out_l, b_out_l
// Output: concat of [w_zero (WZ), b_out_u_ (64), w_zero (WZ), b_out_l_ (64)]
//
// Structure: fork the zero-fill onto TWO side streams (one memset each, so
// the two driver fill kernels can run concurrently and absorb SMs freed when
// the reduce branch finishes); main stream runs pool -> reduce; join both.
// Bias writes and memset ranges are disjoint -> race-free.
// ---------------------------------------------------------------------------
extern "C" void kernel_launch(void* const* d_in, const int* in_sizes, int n_in,
                              void* d_out, int out_size) {
    const float* u_c  = (const float*)d_in[2];
    const float* l_c  = (const float*)d_in[3];
    const float* wu   = (const float*)d_in[4];
    const float* bou  = (const float*)d_in[5];
    const float* wl   = (const float*)d_in[6];
    const float* bol  = (const float*)d_in[7];
    float* out = (float*)d_out;

    if (!g_res_ready) {
        cudaStreamCreateWithFlags(&g_s2, cudaStreamNonBlocking);
        cudaStreamCreateWithFlags(&g_s3, cudaStreamNonBlocking);
        cudaEventCreateWithFlags(&g_evFork,  cudaEventDisableTiming);
        cudaEventCreateWithFlags(&g_evJoin2, cudaEventDisableTiming);
        cudaEventCreateWithFlags(&g_evJoin3, cudaEventDisableTiming);
        g_res_ready = true;
    }

    // ---- fork both side streams off the (possibly capturing) main stream ----
    cudaEventRecord(g_evFork, 0);
    cudaStreamWaitEvent(g_s2, g_evFork, 0);
    cudaStreamWaitEvent(g_s3, g_evFork, 0);

    // ---- branch A (s2): zero-fill region 1, floats [0, WZ) ----
    cudaMemsetAsync(out, 0, (size_t)WZ * sizeof(float), g_s2);
    // ---- branch B (s3): zero-fill region 2, floats [WZ+64, 2WZ+64) ----
    cudaMemsetAsync(out + WZ + 64, 0, (size_t)WZ * sizeof(float), g_s3);

    // ---- branch C (main): pool -> interval reduction + bias writes ----
    pool_kernel<<<BATCH * NPOOL / 256, 256, 0, 0>>>(u_c, l_c);
    reduce_kernel<<<RB, NTHREADS, 0, 0>>>(wu, wl, bou, bol, out);

    // ---- join ----
    cudaEventRecord(g_evJoin2, g_s2);
    cudaEventRecord(g_evJoin3, g_s3);
    cudaStreamWaitEvent(0, g_evJoin2, 0);
    cudaStreamWaitEvent(0, g_evJoin3, 0);
}